// round 5
// baseline (speedup 1.0000x reference)
#include <cuda_runtime.h>

#define NN 50000
#define EE 800000
#define NCLS 40

// ---------------- device scratch (static, allocation-free) ----------------
__device__ __align__(16) float g_H1[NN * 128];    // layer1 features h = x@W1
__device__ __align__(16) float g_out1[NN * 128];  // layer1 output after ELU
__device__ __align__(16) float g_H2[NN * NCLS];   // layer2 features
__device__ __align__(16) float g_asrc1[NN * 8];
__device__ __align__(16) float g_adst1[NN * 8];
__device__ float g_asrc2[NN];
__device__ float g_adst2[NN];
__device__ int g_deg[NN];
__device__ int g_fill[NN];
__device__ int g_rowptr[NN + 1];
__device__ int g_csr[EE];

__device__ __forceinline__ float lrelu(float x) { return x > 0.f ? x : 0.2f * x; }

// ---------------- CSR build ----------------
__global__ void zero_kernel() {
    int i = blockIdx.x * blockDim.x + threadIdx.x;
    if (i < NN) { g_deg[i] = 0; g_fill[i] = 0; }
}

__global__ void count_kernel(const int* __restrict__ ei) {
    int e = blockIdx.x * blockDim.x + threadIdx.x;
    if (e < EE) {
        int d = ei[EE + e];
        atomicAdd(&g_deg[d], 1);
    }
}

__global__ void scan_kernel() {
    __shared__ int sh[1024];
    __shared__ int s_carry;
    int t = threadIdx.x;
    if (t == 0) { s_carry = 0; g_rowptr[0] = 0; }
    __syncthreads();
    for (int base = 0; base < NN; base += 1024) {
        int i = base + t;
        sh[t] = (i < NN) ? g_deg[i] : 0;
        __syncthreads();
        for (int off = 1; off < 1024; off <<= 1) {
            int add = (t >= off) ? sh[t - off] : 0;
            __syncthreads();
            sh[t] += add;
            __syncthreads();
        }
        if (i < NN) g_rowptr[i + 1] = s_carry + sh[t];
        __syncthreads();
        if (t == 0) s_carry += sh[1023];
        __syncthreads();
    }
}

__global__ void fill_kernel(const int* __restrict__ ei) {
    int e = blockIdx.x * blockDim.x + threadIdx.x;
    if (e < EE) {
        int s = ei[e];
        int d = ei[EE + e];
        int pos = atomicAdd(&g_fill[d], 1);
        g_csr[g_rowptr[d] + pos] = s;
    }
}

// ---------------- GEMM1: H1[N,128] = x[N,128] @ W1[128,128] ----------------
// block = 256 threads, 32 nodes/block. x tile + 32-row W chunk in smem.
__global__ void gemm1_kernel(const float* __restrict__ x, const float* __restrict__ W1) {
    __shared__ float sx[32 * 132];   // padded stride to kill bank conflicts
    __shared__ float sw[32 * 128];
    int t = threadIdx.x;
    int nl = t >> 3, cg = t & 7;
    int nbase = blockIdx.x * 32;

#pragma unroll
    for (int i = 0; i < 4; i++) {
        int idx = t + 256 * i;           // float4 index into 32x32 f4 tile
        int r = idx >> 5, c4 = idx & 31;
        int gn = nbase + r;
        float4 v = make_float4(0.f, 0.f, 0.f, 0.f);
        if (gn < NN) v = ((const float4*)x)[gn * 32 + c4];
        float* dst = &sx[r * 132 + c4 * 4];
        dst[0] = v.x; dst[1] = v.y; dst[2] = v.z; dst[3] = v.w;
    }

    float4 acc[4];
#pragma unroll
    for (int g = 0; g < 4; g++) acc[g] = make_float4(0.f, 0.f, 0.f, 0.f);

    for (int kb = 0; kb < 4; kb++) {
        __syncthreads();
#pragma unroll
        for (int i = 0; i < 4; i++) {
            int idx = t + 256 * i;       // 1024 float4 = 32 rows x 128 cols
            ((float4*)sw)[idx] = ((const float4*)W1)[kb * 1024 + idx];
        }
        __syncthreads();
#pragma unroll
        for (int k = 0; k < 32; k++) {
            float xv = sx[nl * 132 + kb * 32 + k];
            const float4* wr = (const float4*)&sw[k * 128];
#pragma unroll
            for (int g = 0; g < 4; g++) {
                float4 wv = wr[cg + 8 * g];
                acc[g].x += xv * wv.x; acc[g].y += xv * wv.y;
                acc[g].z += xv * wv.z; acc[g].w += xv * wv.w;
            }
        }
    }
    int node = nbase + nl;
    if (node < NN) {
#pragma unroll
        for (int g = 0; g < 4; g++)
            ((float4*)g_H1)[node * 32 + 8 * g + cg] = acc[g];
    }
}

// ---------------- per-node attention logits, layer 1 ----------------
__global__ void attn1_kernel(const float* __restrict__ att_src, const float* __restrict__ att_dst) {
    int tg = blockIdx.x * blockDim.x + threadIdx.x;
    int n = tg >> 3, h = tg & 7;
    if (n >= NN) return;
    const float* hp = &g_H1[n * 128 + h * 16];
    const float* sp = &att_src[h * 16];
    const float* dp = &att_dst[h * 16];
    float ss = 0.f, ds = 0.f;
#pragma unroll
    for (int c = 0; c < 16; c++) {
        float v = hp[c];
        ss += v * __ldg(&sp[c]);
        ds += v * __ldg(&dp[c]);
    }
    g_asrc1[n * 8 + h] = ss;
    g_adst1[n * 8 + h] = ds;
}

// ---------------- layer-1 aggregation: warp per destination node ----------------
// lane l owns float4 (4 cols) of the 128-wide output; its head is l>>2.
__global__ void agg1_kernel(const float* __restrict__ b1) {
    int w = (blockIdx.x * blockDim.x + threadIdx.x) >> 5;
    int l = threadIdx.x & 31;
    if (w >= NN) return;
    int d = w;
    int start = g_rowptr[d], end = g_rowptr[d + 1];
    int hl = l >> 2;

    float adv[8], wself[8], den[8];
    {
        float4 a0 = ((const float4*)g_adst1)[d * 2];
        float4 a1 = ((const float4*)g_adst1)[d * 2 + 1];
        adv[0] = a0.x; adv[1] = a0.y; adv[2] = a0.z; adv[3] = a0.w;
        adv[4] = a1.x; adv[5] = a1.y; adv[6] = a1.z; adv[7] = a1.w;
        float4 s0 = ((const float4*)g_asrc1)[d * 2];
        float4 s1 = ((const float4*)g_asrc1)[d * 2 + 1];
        float asv[8] = {s0.x, s0.y, s0.z, s0.w, s1.x, s1.y, s1.z, s1.w};
#pragma unroll
        for (int h = 0; h < 8; h++) {
            wself[h] = __expf(lrelu(asv[h] + adv[h]));
            den[h] = 0.f;
        }
    }

    // pass 1: softmax denominators (lanes stride edges)
    for (int e = start + l; e < end; e += 32) {
        int s = g_csr[e];
        float4 s0 = ((const float4*)g_asrc1)[s * 2];
        float4 s1 = ((const float4*)g_asrc1)[s * 2 + 1];
        float bs[8] = {s0.x, s0.y, s0.z, s0.w, s1.x, s1.y, s1.z, s1.w};
#pragma unroll
        for (int h = 0; h < 8; h++)
            den[h] += __expf(lrelu(bs[h] + adv[h]));
    }
#pragma unroll
    for (int h = 0; h < 8; h++) {
#pragma unroll
        for (int off = 16; off > 0; off >>= 1)
            den[h] += __shfl_xor_sync(0xffffffffu, den[h], off);
    }

    float invh = 1.f / (den[hl] + wself[hl]);
    float adh = adv[hl];

    // self-loop contribution
    float4 acc;
    {
        float cs = wself[hl] * invh;
        float4 v = ((const float4*)g_H1)[d * 32 + l];
        acc.x = cs * v.x; acc.y = cs * v.y; acc.z = cs * v.z; acc.w = cs * v.w;
    }

    // pass 2: whole warp per edge, prefetch next src id
    int s = (start < end) ? g_csr[start] : 0;
    for (int e = start; e < end; e++) {
        int sn = (e + 1 < end) ? g_csr[e + 1] : 0;
        float coef = __expf(lrelu(g_asrc1[s * 8 + hl] + adh)) * invh;
        float4 v = ((const float4*)g_H1)[s * 32 + l];
        acc.x += coef * v.x; acc.y += coef * v.y;
        acc.z += coef * v.z; acc.w += coef * v.w;
        s = sn;
    }

    float4 bb = ((const float4*)b1)[l];
    acc.x += bb.x; acc.y += bb.y; acc.z += bb.z; acc.w += bb.w;
    // ELU
    acc.x = acc.x > 0.f ? acc.x : __expf(acc.x) - 1.f;
    acc.y = acc.y > 0.f ? acc.y : __expf(acc.y) - 1.f;
    acc.z = acc.z > 0.f ? acc.z : __expf(acc.z) - 1.f;
    acc.w = acc.w > 0.f ? acc.w : __expf(acc.w) - 1.f;
    ((float4*)g_out1)[d * 32 + l] = acc;
}

// ---------------- GEMM2: H2[N,40] = out1[N,128] @ W2[128,40] ----------------
__global__ void gemm2_kernel(const float* __restrict__ W2) {
    __shared__ float sx[32 * 132];
    __shared__ float sW[128 * NCLS];
    int t = threadIdx.x;
    int nl = t >> 3, cg = t & 7;   // 8 groups of 5 output cols
    int nbase = blockIdx.x * 32;

#pragma unroll
    for (int i = 0; i < 4; i++) {
        int idx = t + 256 * i;
        int r = idx >> 5, c4 = idx & 31;
        int gn = nbase + r;
        float4 v = make_float4(0.f, 0.f, 0.f, 0.f);
        if (gn < NN) v = ((const float4*)g_out1)[gn * 32 + c4];
        float* dst = &sx[r * 132 + c4 * 4];
        dst[0] = v.x; dst[1] = v.y; dst[2] = v.z; dst[3] = v.w;
    }
    for (int i = t; i < 128 * NCLS; i += 256) sW[i] = W2[i];
    __syncthreads();

    float acc[5] = {0.f, 0.f, 0.f, 0.f, 0.f};
    const float* wp = &sW[cg * 5];
    const float* xp = &sx[nl * 132];
#pragma unroll 4
    for (int k = 0; k < 128; k++) {
        float xv = xp[k];
#pragma unroll
        for (int j = 0; j < 5; j++)
            acc[j] += xv * wp[k * NCLS + j];
    }
    int node = nbase + nl;
    if (node < NN) {
#pragma unroll
        for (int j = 0; j < 5; j++)
            g_H2[node * NCLS + cg * 5 + j] = acc[j];
    }
}

// ---------------- per-node attention logits, layer 2 ----------------
__global__ void attn2_kernel(const float* __restrict__ att_src, const float* __restrict__ att_dst) {
    int n = blockIdx.x * blockDim.x + threadIdx.x;
    if (n >= NN) return;
    const float* hp = &g_H2[n * NCLS];
    float ss = 0.f, ds = 0.f;
#pragma unroll
    for (int c = 0; c < NCLS; c++) {
        float v = hp[c];
        ss += v * __ldg(&att_src[c]);
        ds += v * __ldg(&att_dst[c]);
    }
    g_asrc2[n] = ss;
    g_adst2[n] = ds;
}

// ---------------- layer-2 aggregation: warp per destination node ----------------
__global__ void agg2_kernel(const float* __restrict__ b2, float* __restrict__ out) {
    int w = (blockIdx.x * blockDim.x + threadIdx.x) >> 5;
    int l = threadIdx.x & 31;
    if (w >= NN) return;
    int d = w;
    int start = g_rowptr[d], end = g_rowptr[d + 1];

    float adst = g_adst2[d];
    float wself = __expf(lrelu(g_asrc2[d] + adst));
    float den = 0.f;
    for (int e = start + l; e < end; e += 32)
        den += __expf(lrelu(g_asrc2[g_csr[e]] + adst));
#pragma unroll
    for (int off = 16; off > 0; off >>= 1)
        den += __shfl_xor_sync(0xffffffffu, den, off);
    float inv = 1.f / (den + wself);

    float cs = wself * inv;
    float accA = cs * g_H2[d * NCLS + l];
    float accB = (l < 8) ? cs * g_H2[d * NCLS + 32 + l] : 0.f;

    int s = (start < end) ? g_csr[start] : 0;
    for (int e = start; e < end; e++) {
        int sn = (e + 1 < end) ? g_csr[e + 1] : 0;
        float coef = __expf(lrelu(g_asrc2[s] + adst)) * inv;
        accA += coef * g_H2[s * NCLS + l];
        if (l < 8) accB += coef * g_H2[s * NCLS + 32 + l];
        s = sn;
    }
    out[d * NCLS + l] = accA + b2[l];
    if (l < 8) out[d * NCLS + 32 + l] = accB + b2[32 + l];
}

// ---------------- launch ----------------
extern "C" void kernel_launch(void* const* d_in, const int* in_sizes, int n_in,
                              void* d_out, int out_size) {
    const float* x   = (const float*)d_in[0];
    const int*   ei  = (const int*)d_in[1];     // int32: JAX x64 is disabled
    const float* W1  = (const float*)d_in[2];
    const float* as1 = (const float*)d_in[3];
    const float* ad1 = (const float*)d_in[4];
    const float* b1  = (const float*)d_in[5];
    const float* W2  = (const float*)d_in[6];
    const float* as2 = (const float*)d_in[7];
    const float* ad2 = (const float*)d_in[8];
    const float* b2  = (const float*)d_in[9];
    float* out = (float*)d_out;

    zero_kernel<<<(NN + 255) / 256, 256>>>();
    count_kernel<<<(EE + 255) / 256, 256>>>(ei);
    scan_kernel<<<1, 1024>>>();
    fill_kernel<<<(EE + 255) / 256, 256>>>(ei);

    gemm1_kernel<<<(NN + 31) / 32, 256>>>(x, W1);
    attn1_kernel<<<(NN * 8 + 255) / 256, 256>>>(as1, ad1);
    agg1_kernel<<<(NN * 32 + 255) / 256, 256>>>(b1);

    gemm2_kernel<<<(NN + 31) / 32, 256>>>(W2);
    attn2_kernel<<<(NN + 255) / 256, 256>>>(as2, ad2);
    agg2_kernel<<<(NN * 32 + 255) / 256, 256>>>(b2, out);
}

// round 6
// speedup vs baseline: 1.3410x; 1.3410x over previous
#include <cuda_runtime.h>

#define NN 50000
#define EE 800000
#define NCLS 40
#define NBLK 49   // ceil(NN/1024)

// ---------------- device scratch (static, allocation-free) ----------------
__device__ __align__(16) float g_H1[NN * 128];    // layer1 features h = x@W1
__device__ __align__(16) float g_out1[NN * 128];  // layer1 output after ELU
__device__ __align__(16) float g_H2[NN * NCLS];   // layer2 features
__device__ __align__(16) float g_asrc1[NN * 8];
__device__ __align__(16) float g_adst1[NN * 8];
__device__ float g_asrc2[NN];
__device__ float g_adst2[NN];
__device__ int g_deg[NN];
__device__ int g_fill[NN];
__device__ int g_rowptr[NN + 1];
__device__ int g_csr[EE];
__device__ int g_bsum[64];
__device__ int g_boff[64];

__device__ __forceinline__ float lrelu(float x) { return x > 0.f ? x : 0.2f * x; }

// ---------------- CSR build ----------------
__global__ void zero_kernel() {
    int i = blockIdx.x * blockDim.x + threadIdx.x;
    if (i < NN) { g_deg[i] = 0; g_fill[i] = 0; }
}

__global__ void count_kernel(const int* __restrict__ ei) {
    int e = blockIdx.x * blockDim.x + threadIdx.x;
    if (e < EE) atomicAdd(&g_deg[ei[EE + e]], 1);
}

// multi-block scan, stage 1: per-block inclusive scan via warp shuffles
__global__ void blockscan_kernel() {
    __shared__ int wsum[32];
    int b = blockIdx.x, t = threadIdx.x;
    int i = b * 1024 + t;
    int lane = t & 31, wid = t >> 5;
    int x = (i < NN) ? g_deg[i] : 0;
#pragma unroll
    for (int off = 1; off < 32; off <<= 1) {
        int y = __shfl_up_sync(0xffffffffu, x, off);
        if (lane >= off) x += y;
    }
    if (lane == 31) wsum[wid] = x;
    __syncthreads();
    if (wid == 0) {
        int s = wsum[lane];
#pragma unroll
        for (int off = 1; off < 32; off <<= 1) {
            int y = __shfl_up_sync(0xffffffffu, s, off);
            if (lane >= off) s += y;
        }
        wsum[lane] = s;
    }
    __syncthreads();
    int incl = x + (wid > 0 ? wsum[wid - 1] : 0);
    if (i < NN) g_rowptr[i + 1] = incl;   // local inclusive scan
    if (t == 1023) g_bsum[b] = incl;      // block total (padding is zero)
}

// stage 2: scan the 49 block sums (one tiny block)
__global__ void scanbsum_kernel() {
    __shared__ int sh[64];
    int t = threadIdx.x;
    sh[t] = (t < NBLK) ? g_bsum[t] : 0;
    __syncthreads();
#pragma unroll
    for (int off = 1; off < 64; off <<= 1) {
        int a = (t >= off) ? sh[t - off] : 0;
        __syncthreads();
        sh[t] += a;
        __syncthreads();
    }
    if (t < NBLK) g_boff[t] = t ? sh[t - 1] : 0;  // exclusive block offsets
}

// stage 3: add block offsets
__global__ void addoff_kernel() {
    int i = blockIdx.x * blockDim.x + threadIdx.x;
    if (i < NN) g_rowptr[i + 1] += g_boff[i >> 10];
    if (i == 0) g_rowptr[0] = 0;
}

__global__ void fill_kernel(const int* __restrict__ ei) {
    int e = blockIdx.x * blockDim.x + threadIdx.x;
    if (e < EE) {
        int s = ei[e];
        int d = ei[EE + e];
        int pos = atomicAdd(&g_fill[d], 1);
        g_csr[g_rowptr[d] + pos] = s;
    }
}

// ---------------- GEMM1: H1[N,128] = x[N,128] @ W1[128,128] ----------------
__global__ void gemm1_kernel(const float* __restrict__ x, const float* __restrict__ W1) {
    __shared__ float sx[32 * 132];   // padded stride to kill bank conflicts
    __shared__ float sw[32 * 128];
    int t = threadIdx.x;
    int nl = t >> 3, cg = t & 7;
    int nbase = blockIdx.x * 32;

#pragma unroll
    for (int i = 0; i < 4; i++) {
        int idx = t + 256 * i;
        int r = idx >> 5, c4 = idx & 31;
        int gn = nbase + r;
        float4 v = make_float4(0.f, 0.f, 0.f, 0.f);
        if (gn < NN) v = ((const float4*)x)[gn * 32 + c4];
        float* dst = &sx[r * 132 + c4 * 4];
        dst[0] = v.x; dst[1] = v.y; dst[2] = v.z; dst[3] = v.w;
    }

    float4 acc[4];
#pragma unroll
    for (int g = 0; g < 4; g++) acc[g] = make_float4(0.f, 0.f, 0.f, 0.f);

    for (int kb = 0; kb < 4; kb++) {
        __syncthreads();
#pragma unroll
        for (int i = 0; i < 4; i++) {
            int idx = t + 256 * i;
            ((float4*)sw)[idx] = ((const float4*)W1)[kb * 1024 + idx];
        }
        __syncthreads();
#pragma unroll
        for (int k = 0; k < 32; k++) {
            float xv = sx[nl * 132 + kb * 32 + k];
            const float4* wr = (const float4*)&sw[k * 128];
#pragma unroll
            for (int g = 0; g < 4; g++) {
                float4 wv = wr[cg + 8 * g];
                acc[g].x += xv * wv.x; acc[g].y += xv * wv.y;
                acc[g].z += xv * wv.z; acc[g].w += xv * wv.w;
            }
        }
    }
    int node = nbase + nl;
    if (node < NN) {
#pragma unroll
        for (int g = 0; g < 4; g++)
            ((float4*)g_H1)[node * 32 + 8 * g + cg] = acc[g];
    }
}

// ---------------- per-node attention logits, layer 1 ----------------
__global__ void attn1_kernel(const float* __restrict__ att_src, const float* __restrict__ att_dst) {
    int tg = blockIdx.x * blockDim.x + threadIdx.x;
    int n = tg >> 3, h = tg & 7;
    if (n >= NN) return;
    const float* hp = &g_H1[n * 128 + h * 16];
    const float* sp = &att_src[h * 16];
    const float* dp = &att_dst[h * 16];
    float ss = 0.f, ds = 0.f;
#pragma unroll
    for (int c = 0; c < 16; c++) {
        float v = hp[c];
        ss += v * __ldg(&sp[c]);
        ds += v * __ldg(&dp[c]);
    }
    g_asrc1[n * 8 + h] = ss;
    g_adst1[n * 8 + h] = ds;
}

// ---------------- layer-1 aggregation: warp per dst, SINGLE edge pass ----------------
// Unnormalized accumulation: acc = sum_e exp(alpha_e) * v_e, den = sum_e exp(alpha_e).
// Every lane iterates every edge, so den needs no warp reduction.
__global__ void agg1_kernel(const float* __restrict__ b1) {
    int w = (blockIdx.x * blockDim.x + threadIdx.x) >> 5;
    int l = threadIdx.x & 31;
    if (w >= NN) return;
    int d = w;
    int start = g_rowptr[d], end = g_rowptr[d + 1];
    int hl = l >> 2;

    float adh = __ldg(&g_adst1[d * 8 + hl]);
    float wself = __expf(lrelu(__ldg(&g_asrc1[d * 8 + hl]) + adh));

    float den0 = wself, den1 = 0.f;
    float4 acc0, acc1;
    {
        float4 v = __ldg(((const float4*)g_H1) + d * 32 + l);
        acc0.x = wself * v.x; acc0.y = wself * v.y;
        acc0.z = wself * v.z; acc0.w = wself * v.w;
        acc1 = make_float4(0.f, 0.f, 0.f, 0.f);
    }

    int e = start;
    for (; e + 1 < end; e += 2) {
        int s0 = g_csr[e];
        int s1 = g_csr[e + 1];
        float w0 = __expf(lrelu(__ldg(&g_asrc1[s0 * 8 + hl]) + adh));
        float w1 = __expf(lrelu(__ldg(&g_asrc1[s1 * 8 + hl]) + adh));
        float4 v0 = __ldg(((const float4*)g_H1) + s0 * 32 + l);
        float4 v1 = __ldg(((const float4*)g_H1) + s1 * 32 + l);
        den0 += w0; den1 += w1;
        acc0.x += w0 * v0.x; acc0.y += w0 * v0.y;
        acc0.z += w0 * v0.z; acc0.w += w0 * v0.w;
        acc1.x += w1 * v1.x; acc1.y += w1 * v1.y;
        acc1.z += w1 * v1.z; acc1.w += w1 * v1.w;
    }
    if (e < end) {
        int s0 = g_csr[e];
        float w0 = __expf(lrelu(__ldg(&g_asrc1[s0 * 8 + hl]) + adh));
        float4 v0 = __ldg(((const float4*)g_H1) + s0 * 32 + l);
        den0 += w0;
        acc0.x += w0 * v0.x; acc0.y += w0 * v0.y;
        acc0.z += w0 * v0.z; acc0.w += w0 * v0.w;
    }

    float inv = 1.f / (den0 + den1);
    float4 bb = ((const float4*)b1)[l];
    float4 r;
    r.x = (acc0.x + acc1.x) * inv + bb.x;
    r.y = (acc0.y + acc1.y) * inv + bb.y;
    r.z = (acc0.z + acc1.z) * inv + bb.z;
    r.w = (acc0.w + acc1.w) * inv + bb.w;
    // ELU
    r.x = r.x > 0.f ? r.x : __expf(r.x) - 1.f;
    r.y = r.y > 0.f ? r.y : __expf(r.y) - 1.f;
    r.z = r.z > 0.f ? r.z : __expf(r.z) - 1.f;
    r.w = r.w > 0.f ? r.w : __expf(r.w) - 1.f;
    ((float4*)g_out1)[d * 32 + l] = r;
}

// ---------------- GEMM2: H2[N,40] = out1[N,128] @ W2[128,40] ----------------
__global__ void gemm2_kernel(const float* __restrict__ W2) {
    __shared__ float sx[32 * 132];
    __shared__ float sW[128 * NCLS];
    int t = threadIdx.x;
    int nl = t >> 3, cg = t & 7;   // 8 groups of 5 output cols
    int nbase = blockIdx.x * 32;

#pragma unroll
    for (int i = 0; i < 4; i++) {
        int idx = t + 256 * i;
        int r = idx >> 5, c4 = idx & 31;
        int gn = nbase + r;
        float4 v = make_float4(0.f, 0.f, 0.f, 0.f);
        if (gn < NN) v = ((const float4*)g_out1)[gn * 32 + c4];
        float* dst = &sx[r * 132 + c4 * 4];
        dst[0] = v.x; dst[1] = v.y; dst[2] = v.z; dst[3] = v.w;
    }
    for (int i = t; i < 128 * NCLS; i += 256) sW[i] = W2[i];
    __syncthreads();

    float acc[5] = {0.f, 0.f, 0.f, 0.f, 0.f};
    const float* wp = &sW[cg * 5];
    const float* xp = &sx[nl * 132];
#pragma unroll 4
    for (int k = 0; k < 128; k++) {
        float xv = xp[k];
#pragma unroll
        for (int j = 0; j < 5; j++)
            acc[j] += xv * wp[k * NCLS + j];
    }
    int node = nbase + nl;
    if (node < NN) {
#pragma unroll
        for (int j = 0; j < 5; j++)
            g_H2[node * NCLS + cg * 5 + j] = acc[j];
    }
}

// ---------------- per-node attention logits, layer 2 ----------------
__global__ void attn2_kernel(const float* __restrict__ att_src, const float* __restrict__ att_dst) {
    int n = blockIdx.x * blockDim.x + threadIdx.x;
    if (n >= NN) return;
    const float* hp = &g_H2[n * NCLS];
    float ss = 0.f, ds = 0.f;
#pragma unroll
    for (int c = 0; c < NCLS; c++) {
        float v = hp[c];
        ss += v * __ldg(&att_src[c]);
        ds += v * __ldg(&att_dst[c]);
    }
    g_asrc2[n] = ss;
    g_adst2[n] = ds;
}

// ---------------- layer-2 aggregation: warp per dst, single pass ----------------
__global__ void agg2_kernel(const float* __restrict__ b2, float* __restrict__ out) {
    int w = (blockIdx.x * blockDim.x + threadIdx.x) >> 5;
    int l = threadIdx.x & 31;
    if (w >= NN) return;
    int d = w;
    int start = g_rowptr[d], end = g_rowptr[d + 1];

    float adst = __ldg(&g_adst2[d]);
    float wself = __expf(lrelu(__ldg(&g_asrc2[d]) + adst));

    float den0 = wself, den1 = 0.f;
    float accA0 = wself * __ldg(&g_H2[d * NCLS + l]);
    float accA1 = 0.f;
    float accB0 = (l < 8) ? wself * __ldg(&g_H2[d * NCLS + 32 + l]) : 0.f;
    float accB1 = 0.f;

    int e = start;
    for (; e + 1 < end; e += 2) {
        int s0 = g_csr[e];
        int s1 = g_csr[e + 1];
        float w0 = __expf(lrelu(__ldg(&g_asrc2[s0]) + adst));
        float w1 = __expf(lrelu(__ldg(&g_asrc2[s1]) + adst));
        den0 += w0; den1 += w1;
        accA0 += w0 * __ldg(&g_H2[s0 * NCLS + l]);
        accA1 += w1 * __ldg(&g_H2[s1 * NCLS + l]);
        if (l < 8) {
            accB0 += w0 * __ldg(&g_H2[s0 * NCLS + 32 + l]);
            accB1 += w1 * __ldg(&g_H2[s1 * NCLS + 32 + l]);
        }
    }
    if (e < end) {
        int s0 = g_csr[e];
        float w0 = __expf(lrelu(__ldg(&g_asrc2[s0]) + adst));
        den0 += w0;
        accA0 += w0 * __ldg(&g_H2[s0 * NCLS + l]);
        if (l < 8) accB0 += w0 * __ldg(&g_H2[s0 * NCLS + 32 + l]);
    }

    float inv = 1.f / (den0 + den1);
    out[d * NCLS + l] = (accA0 + accA1) * inv + b2[l];
    if (l < 8) out[d * NCLS + 32 + l] = (accB0 + accB1) * inv + b2[32 + l];
}

// ---------------- launch ----------------
extern "C" void kernel_launch(void* const* d_in, const int* in_sizes, int n_in,
                              void* d_out, int out_size) {
    const float* x   = (const float*)d_in[0];
    const int*   ei  = (const int*)d_in[1];     // int32 (JAX x64 disabled)
    const float* W1  = (const float*)d_in[2];
    const float* as1 = (const float*)d_in[3];
    const float* ad1 = (const float*)d_in[4];
    const float* b1  = (const float*)d_in[5];
    const float* W2  = (const float*)d_in[6];
    const float* as2 = (const float*)d_in[7];
    const float* ad2 = (const float*)d_in[8];
    const float* b2  = (const float*)d_in[9];
    float* out = (float*)d_out;

    zero_kernel<<<(NN + 255) / 256, 256>>>();
    count_kernel<<<(EE + 255) / 256, 256>>>(ei);
    blockscan_kernel<<<NBLK, 1024>>>();
    scanbsum_kernel<<<1, 64>>>();
    addoff_kernel<<<(NN + 255) / 256, 256>>>();
    fill_kernel<<<(EE + 255) / 256, 256>>>(ei);

    gemm1_kernel<<<(NN + 31) / 32, 256>>>(x, W1);
    attn1_kernel<<<(NN * 8 + 255) / 256, 256>>>(as1, ad1);
    agg1_kernel<<<(NN * 32 + 255) / 256, 256>>>(b1);

    gemm2_kernel<<<(NN + 31) / 32, 256>>>(W2);
    attn2_kernel<<<(NN + 255) / 256, 256>>>(as2, ad2);
    agg2_kernel<<<(NN * 32 + 255) / 256, 256>>>(b2, out);
}

// round 7
// speedup vs baseline: 1.3854x; 1.0331x over previous
#include <cuda_runtime.h>

#define NN 50000
#define EE 800000
#define NCLS 40
#define NBLK 49   // ceil(NN/1024)

// ---------------- device scratch (static, allocation-free) ----------------
__device__ __align__(16) float g_H1[NN * 128];    // layer1 features h = x@W1
__device__ __align__(16) float g_out1[NN * 128];  // layer1 output after ELU
__device__ __align__(16) float g_H2[NN * NCLS];   // layer2 features
__device__ __align__(16) float g_asrc1[NN * 8];
__device__ __align__(16) float g_adst1[NN * 8];
__device__ float g_asrc2[NN];
__device__ float g_adst2[NN];
__device__ int g_deg[NN];
__device__ int g_fill[NN];
__device__ int g_rowptr[NN + 1];
__device__ int g_csr[EE];
__device__ int g_bsum[64];
__device__ int g_boff[64];

__device__ __forceinline__ float lrelu(float x) { return x > 0.f ? x : 0.2f * x; }

// ---------------- CSR build ----------------
__global__ void zero_kernel() {
    int i = blockIdx.x * blockDim.x + threadIdx.x;
    if (i < NN) { g_deg[i] = 0; g_fill[i] = 0; }
}

__global__ void count_kernel(const int* __restrict__ ei) {
    int e = blockIdx.x * blockDim.x + threadIdx.x;
    if (e < EE) atomicAdd(&g_deg[ei[EE + e]], 1);
}

// multi-block scan, stage 1: per-block inclusive scan via warp shuffles
__global__ void blockscan_kernel() {
    __shared__ int wsum[32];
    int b = blockIdx.x, t = threadIdx.x;
    int i = b * 1024 + t;
    int lane = t & 31, wid = t >> 5;
    int x = (i < NN) ? g_deg[i] : 0;
#pragma unroll
    for (int off = 1; off < 32; off <<= 1) {
        int y = __shfl_up_sync(0xffffffffu, x, off);
        if (lane >= off) x += y;
    }
    if (lane == 31) wsum[wid] = x;
    __syncthreads();
    if (wid == 0) {
        int s = wsum[lane];
#pragma unroll
        for (int off = 1; off < 32; off <<= 1) {
            int y = __shfl_up_sync(0xffffffffu, s, off);
            if (lane >= off) s += y;
        }
        wsum[lane] = s;
    }
    __syncthreads();
    int incl = x + (wid > 0 ? wsum[wid - 1] : 0);
    if (i < NN) g_rowptr[i + 1] = incl;   // local inclusive scan
    if (t == 1023) g_bsum[b] = incl;      // block total (padding is zero)
}

// stage 2: scan the 49 block sums (one tiny block)
__global__ void scanbsum_kernel() {
    __shared__ int sh[64];
    int t = threadIdx.x;
    sh[t] = (t < NBLK) ? g_bsum[t] : 0;
    __syncthreads();
#pragma unroll
    for (int off = 1; off < 64; off <<= 1) {
        int a = (t >= off) ? sh[t - off] : 0;
        __syncthreads();
        sh[t] += a;
        __syncthreads();
    }
    if (t < NBLK) g_boff[t] = t ? sh[t - 1] : 0;  // exclusive block offsets
}

// stage 3: add block offsets
__global__ void addoff_kernel() {
    int i = blockIdx.x * blockDim.x + threadIdx.x;
    if (i < NN) g_rowptr[i + 1] += g_boff[i >> 10];
    if (i == 0) g_rowptr[0] = 0;
}

__global__ void fill_kernel(const int* __restrict__ ei) {
    int e = blockIdx.x * blockDim.x + threadIdx.x;
    if (e < EE) {
        int s = ei[e];
        int d = ei[EE + e];
        int pos = atomicAdd(&g_fill[d], 1);
        g_csr[g_rowptr[d] + pos] = s;
    }
}

// ---------------- GEMM1: H1[N,128] = x[N,128] @ W1[128,128] ----------------
__global__ void gemm1_kernel(const float* __restrict__ x, const float* __restrict__ W1) {
    __shared__ float sx[32 * 132];   // padded stride to kill bank conflicts
    __shared__ float sw[32 * 128];
    int t = threadIdx.x;
    int nl = t >> 3, cg = t & 7;
    int nbase = blockIdx.x * 32;

#pragma unroll
    for (int i = 0; i < 4; i++) {
        int idx = t + 256 * i;
        int r = idx >> 5, c4 = idx & 31;
        int gn = nbase + r;
        float4 v = make_float4(0.f, 0.f, 0.f, 0.f);
        if (gn < NN) v = ((const float4*)x)[gn * 32 + c4];
        float* dst = &sx[r * 132 + c4 * 4];
        dst[0] = v.x; dst[1] = v.y; dst[2] = v.z; dst[3] = v.w;
    }

    float4 acc[4];
#pragma unroll
    for (int g = 0; g < 4; g++) acc[g] = make_float4(0.f, 0.f, 0.f, 0.f);

    for (int kb = 0; kb < 4; kb++) {
        __syncthreads();
#pragma unroll
        for (int i = 0; i < 4; i++) {
            int idx = t + 256 * i;
            ((float4*)sw)[idx] = ((const float4*)W1)[kb * 1024 + idx];
        }
        __syncthreads();
#pragma unroll
        for (int k = 0; k < 32; k++) {
            float xv = sx[nl * 132 + kb * 32 + k];
            const float4* wr = (const float4*)&sw[k * 128];
#pragma unroll
            for (int g = 0; g < 4; g++) {
                float4 wv = wr[cg + 8 * g];
                acc[g].x += xv * wv.x; acc[g].y += xv * wv.y;
                acc[g].z += xv * wv.z; acc[g].w += xv * wv.w;
            }
        }
    }
    int node = nbase + nl;
    if (node < NN) {
#pragma unroll
        for (int g = 0; g < 4; g++)
            ((float4*)g_H1)[node * 32 + 8 * g + cg] = acc[g];
    }
}

// ---------------- per-node attention logits, layer 1 ----------------
__global__ void attn1_kernel(const float* __restrict__ att_src, const float* __restrict__ att_dst) {
    int tg = blockIdx.x * blockDim.x + threadIdx.x;
    int n = tg >> 3, h = tg & 7;
    if (n >= NN) return;
    const float* hp = &g_H1[n * 128 + h * 16];
    const float* sp = &att_src[h * 16];
    const float* dp = &att_dst[h * 16];
    float ss = 0.f, ds = 0.f;
#pragma unroll
    for (int c = 0; c < 16; c++) {
        float v = hp[c];
        ss += v * __ldg(&sp[c]);
        ds += v * __ldg(&dp[c]);
    }
    g_asrc1[n * 8 + h] = ss;
    g_adst1[n * 8 + h] = ds;
}

// ---------------- layer-1 aggregation: warp per dst, SINGLE edge pass, unroll 4 ----
// Unnormalized accumulation: acc = sum_e exp(alpha_e)*v_e, den = sum_e exp(alpha_e).
__global__ void agg1_kernel(const float* __restrict__ b1) {
    int w = (blockIdx.x * blockDim.x + threadIdx.x) >> 5;
    int l = threadIdx.x & 31;
    if (w >= NN) return;
    int d = w;
    int start = g_rowptr[d], end = g_rowptr[d + 1];
    int hl = l >> 2;

    float adh = __ldg(&g_adst1[d * 8 + hl]);
    float wself = __expf(lrelu(__ldg(&g_asrc1[d * 8 + hl]) + adh));

    float den0 = wself, den1 = 0.f, den2 = 0.f, den3 = 0.f;
    float4 acc0, acc1, acc2, acc3;
    {
        float4 v = __ldg(((const float4*)g_H1) + d * 32 + l);
        acc0.x = wself * v.x; acc0.y = wself * v.y;
        acc0.z = wself * v.z; acc0.w = wself * v.w;
        acc1 = make_float4(0.f, 0.f, 0.f, 0.f);
        acc2 = make_float4(0.f, 0.f, 0.f, 0.f);
        acc3 = make_float4(0.f, 0.f, 0.f, 0.f);
    }

    int e = start;
    for (; e + 3 < end; e += 4) {
        int s0 = g_csr[e];
        int s1 = g_csr[e + 1];
        int s2 = g_csr[e + 2];
        int s3 = g_csr[e + 3];
        float w0 = __expf(lrelu(__ldg(&g_asrc1[s0 * 8 + hl]) + adh));
        float w1 = __expf(lrelu(__ldg(&g_asrc1[s1 * 8 + hl]) + adh));
        float w2 = __expf(lrelu(__ldg(&g_asrc1[s2 * 8 + hl]) + adh));
        float w3 = __expf(lrelu(__ldg(&g_asrc1[s3 * 8 + hl]) + adh));
        float4 v0 = __ldg(((const float4*)g_H1) + s0 * 32 + l);
        float4 v1 = __ldg(((const float4*)g_H1) + s1 * 32 + l);
        float4 v2 = __ldg(((const float4*)g_H1) + s2 * 32 + l);
        float4 v3 = __ldg(((const float4*)g_H1) + s3 * 32 + l);
        den0 += w0; den1 += w1; den2 += w2; den3 += w3;
        acc0.x += w0 * v0.x; acc0.y += w0 * v0.y; acc0.z += w0 * v0.z; acc0.w += w0 * v0.w;
        acc1.x += w1 * v1.x; acc1.y += w1 * v1.y; acc1.z += w1 * v1.z; acc1.w += w1 * v1.w;
        acc2.x += w2 * v2.x; acc2.y += w2 * v2.y; acc2.z += w2 * v2.z; acc2.w += w2 * v2.w;
        acc3.x += w3 * v3.x; acc3.y += w3 * v3.y; acc3.z += w3 * v3.z; acc3.w += w3 * v3.w;
    }
    for (; e < end; e++) {
        int s0 = g_csr[e];
        float w0 = __expf(lrelu(__ldg(&g_asrc1[s0 * 8 + hl]) + adh));
        float4 v0 = __ldg(((const float4*)g_H1) + s0 * 32 + l);
        den0 += w0;
        acc0.x += w0 * v0.x; acc0.y += w0 * v0.y;
        acc0.z += w0 * v0.z; acc0.w += w0 * v0.w;
    }

    float inv = 1.f / ((den0 + den1) + (den2 + den3));
    float4 bb = ((const float4*)b1)[l];
    float4 r;
    r.x = ((acc0.x + acc1.x) + (acc2.x + acc3.x)) * inv + bb.x;
    r.y = ((acc0.y + acc1.y) + (acc2.y + acc3.y)) * inv + bb.y;
    r.z = ((acc0.z + acc1.z) + (acc2.z + acc3.z)) * inv + bb.z;
    r.w = ((acc0.w + acc1.w) + (acc2.w + acc3.w)) * inv + bb.w;
    // ELU
    r.x = r.x > 0.f ? r.x : __expf(r.x) - 1.f;
    r.y = r.y > 0.f ? r.y : __expf(r.y) - 1.f;
    r.z = r.z > 0.f ? r.z : __expf(r.z) - 1.f;
    r.w = r.w > 0.f ? r.w : __expf(r.w) - 1.f;
    ((float4*)g_out1)[d * 32 + l] = r;
}

// ---------------- GEMM2: H2[N,40] = out1[N,128] @ W2[128,40] ----------------
__global__ void gemm2_kernel(const float* __restrict__ W2) {
    __shared__ float sx[32 * 132];
    __shared__ float sW[128 * NCLS];
    int t = threadIdx.x;
    int nl = t >> 3, cg = t & 7;   // 8 groups of 5 output cols
    int nbase = blockIdx.x * 32;

#pragma unroll
    for (int i = 0; i < 4; i++) {
        int idx = t + 256 * i;
        int r = idx >> 5, c4 = idx & 31;
        int gn = nbase + r;
        float4 v = make_float4(0.f, 0.f, 0.f, 0.f);
        if (gn < NN) v = ((const float4*)g_out1)[gn * 32 + c4];
        float* dst = &sx[r * 132 + c4 * 4];
        dst[0] = v.x; dst[1] = v.y; dst[2] = v.z; dst[3] = v.w;
    }
    for (int i = t; i < 128 * NCLS; i += 256) sW[i] = W2[i];
    __syncthreads();

    float acc[5] = {0.f, 0.f, 0.f, 0.f, 0.f};
    const float* wp = &sW[cg * 5];
    const float* xp = &sx[nl * 132];
#pragma unroll 4
    for (int k = 0; k < 128; k++) {
        float xv = xp[k];
#pragma unroll
        for (int j = 0; j < 5; j++)
            acc[j] += xv * wp[k * NCLS + j];
    }
    int node = nbase + nl;
    if (node < NN) {
#pragma unroll
        for (int j = 0; j < 5; j++)
            g_H2[node * NCLS + cg * 5 + j] = acc[j];
    }
}

// ---------------- per-node attention logits, layer 2 ----------------
__global__ void attn2_kernel(const float* __restrict__ att_src, const float* __restrict__ att_dst) {
    int n = blockIdx.x * blockDim.x + threadIdx.x;
    if (n >= NN) return;
    const float* hp = &g_H2[n * NCLS];
    float ss = 0.f, ds = 0.f;
#pragma unroll
    for (int c = 0; c < NCLS; c++) {
        float v = hp[c];
        ss += v * __ldg(&att_src[c]);
        ds += v * __ldg(&att_dst[c]);
    }
    g_asrc2[n] = ss;
    g_adst2[n] = ds;
}

// ---------------- layer-2 aggregation: warp per dst, single pass ----------------
__global__ void agg2_kernel(const float* __restrict__ b2, float* __restrict__ out) {
    int w = (blockIdx.x * blockDim.x + threadIdx.x) >> 5;
    int l = threadIdx.x & 31;
    if (w >= NN) return;
    int d = w;
    int start = g_rowptr[d], end = g_rowptr[d + 1];

    float adst = __ldg(&g_adst2[d]);
    float wself = __expf(lrelu(__ldg(&g_asrc2[d]) + adst));

    float den0 = wself, den1 = 0.f;
    float accA0 = wself * __ldg(&g_H2[d * NCLS + l]);
    float accA1 = 0.f;
    float accB0 = (l < 8) ? wself * __ldg(&g_H2[d * NCLS + 32 + l]) : 0.f;
    float accB1 = 0.f;

    int e = start;
    for (; e + 1 < end; e += 2) {
        int s0 = g_csr[e];
        int s1 = g_csr[e + 1];
        float w0 = __expf(lrelu(__ldg(&g_asrc2[s0]) + adst));
        float w1 = __expf(lrelu(__ldg(&g_asrc2[s1]) + adst));
        den0 += w0; den1 += w1;
        accA0 += w0 * __ldg(&g_H2[s0 * NCLS + l]);
        accA1 += w1 * __ldg(&g_H2[s1 * NCLS + l]);
        if (l < 8) {
            accB0 += w0 * __ldg(&g_H2[s0 * NCLS + 32 + l]);
            accB1 += w1 * __ldg(&g_H2[s1 * NCLS + 32 + l]);
        }
    }
    if (e < end) {
        int s0 = g_csr[e];
        float w0 = __expf(lrelu(__ldg(&g_asrc2[s0]) + adst));
        den0 += w0;
        accA0 += w0 * __ldg(&g_H2[s0 * NCLS + l]);
        if (l < 8) accB0 += w0 * __ldg(&g_H2[s0 * NCLS + 32 + l]);
    }

    float inv = 1.f / (den0 + den1);
    out[d * NCLS + l] = (accA0 + accA1) * inv + b2[l];
    if (l < 8) out[d * NCLS + 32 + l] = (accB0 + accB1) * inv + b2[32 + l];
}

// ---------------- launch: CSR build overlapped with GEMM1/attn1 ----------------
static cudaStream_t g_s2 = nullptr;
static cudaEvent_t g_evFork = nullptr, g_evJoin = nullptr;

extern "C" void kernel_launch(void* const* d_in, const int* in_sizes, int n_in,
                              void* d_out, int out_size) {
    const float* x   = (const float*)d_in[0];
    const int*   ei  = (const int*)d_in[1];     // int32 (JAX x64 disabled)
    const float* W1  = (const float*)d_in[2];
    const float* as1 = (const float*)d_in[3];
    const float* ad1 = (const float*)d_in[4];
    const float* b1  = (const float*)d_in[5];
    const float* W2  = (const float*)d_in[6];
    const float* as2 = (const float*)d_in[7];
    const float* ad2 = (const float*)d_in[8];
    const float* b2  = (const float*)d_in[9];
    float* out = (float*)d_out;

    if (g_s2 == nullptr) {
        cudaStreamCreateWithFlags(&g_s2, cudaStreamNonBlocking);
        cudaEventCreateWithFlags(&g_evFork, cudaEventDisableTiming);
        cudaEventCreateWithFlags(&g_evJoin, cudaEventDisableTiming);
    }

    // fork: CSR build on side stream
    cudaEventRecord(g_evFork, 0);
    cudaStreamWaitEvent(g_s2, g_evFork, 0);

    zero_kernel<<<(NN + 255) / 256, 256, 0, g_s2>>>();
    count_kernel<<<(EE + 255) / 256, 256, 0, g_s2>>>(ei);
    blockscan_kernel<<<NBLK, 1024, 0, g_s2>>>();
    scanbsum_kernel<<<1, 64, 0, g_s2>>>();
    addoff_kernel<<<(NN + 255) / 256, 256, 0, g_s2>>>();
    fill_kernel<<<(EE + 255) / 256, 256, 0, g_s2>>>(ei);
    cudaEventRecord(g_evJoin, g_s2);

    // main stream: dense work that doesn't need the CSR
    gemm1_kernel<<<(NN + 31) / 32, 256>>>(x, W1);
    attn1_kernel<<<(NN * 8 + 255) / 256, 256>>>(as1, ad1);

    // join: aggregation needs both
    cudaStreamWaitEvent(0, g_evJoin, 0);
    agg1_kernel<<<(NN * 32 + 255) / 256, 256>>>(b1);

    gemm2_kernel<<<(NN + 31) / 32, 256>>>(W2);
    attn2_kernel<<<(NN + 255) / 256, 256>>>(as2, ad2);
    agg2_kernel<<<(NN * 32 + 255) / 256, 256>>>(b2, out);
}

// round 9
// speedup vs baseline: 2.2048x; 1.5914x over previous
#include <cuda_runtime.h>
#include <cuda_bf16.h>
#include <cstdint>

#define NN 50000
#define EE 800000
#define NCLS 40
#define NBLK 49   // ceil(NN/1024)

// ---------------- device scratch (static, allocation-free) ----------------
__device__ __align__(16) float g_H1[NN * 128];    // layer1 features h = x@W1
__device__ __align__(16) float g_out1[NN * 128];  // layer1 output after ELU
__device__ __align__(16) float g_H2[NN * NCLS];   // layer2 features
__device__ __align__(16) float g_asrc1[NN * 8];
__device__ __align__(16) float g_adst1[NN * 8];
__device__ float g_asrc2[NN];
__device__ float g_adst2[NN];
__device__ int g_deg[NN];
__device__ int g_fill[NN];
__device__ int g_rowptr[NN + 1];
__device__ int g_csr[EE];
__device__ int g_bsum[64];
__device__ int g_boff[64];

__device__ __forceinline__ float lrelu(float x) { return x > 0.f ? x : 0.2f * x; }

// ---------------- CSR build ----------------
__global__ void zero_kernel() {
    int i = blockIdx.x * blockDim.x + threadIdx.x;
    if (i < NN) { g_deg[i] = 0; g_fill[i] = 0; }
}

__global__ void count_kernel(const int* __restrict__ ei) {
    int e = blockIdx.x * blockDim.x + threadIdx.x;
    if (e < EE) atomicAdd(&g_deg[ei[EE + e]], 1);
}

__global__ void blockscan_kernel() {
    __shared__ int wsum[32];
    int b = blockIdx.x, t = threadIdx.x;
    int i = b * 1024 + t;
    int lane = t & 31, wid = t >> 5;
    int x = (i < NN) ? g_deg[i] : 0;
#pragma unroll
    for (int off = 1; off < 32; off <<= 1) {
        int y = __shfl_up_sync(0xffffffffu, x, off);
        if (lane >= off) x += y;
    }
    if (lane == 31) wsum[wid] = x;
    __syncthreads();
    if (wid == 0) {
        int s = wsum[lane];
#pragma unroll
        for (int off = 1; off < 32; off <<= 1) {
            int y = __shfl_up_sync(0xffffffffu, s, off);
            if (lane >= off) s += y;
        }
        wsum[lane] = s;
    }
    __syncthreads();
    int incl = x + (wid > 0 ? wsum[wid - 1] : 0);
    if (i < NN) g_rowptr[i + 1] = incl;
    if (t == 1023) g_bsum[b] = incl;
}

__global__ void scanbsum_kernel() {
    __shared__ int sh[64];
    int t = threadIdx.x;
    sh[t] = (t < NBLK) ? g_bsum[t] : 0;
    __syncthreads();
#pragma unroll
    for (int off = 1; off < 64; off <<= 1) {
        int a = (t >= off) ? sh[t - off] : 0;
        __syncthreads();
        sh[t] += a;
        __syncthreads();
    }
    if (t < NBLK) g_boff[t] = t ? sh[t - 1] : 0;
}

__global__ void addoff_kernel() {
    int i = blockIdx.x * blockDim.x + threadIdx.x;
    if (i < NN) g_rowptr[i + 1] += g_boff[i >> 10];
    if (i == 0) g_rowptr[0] = 0;
}

__global__ void fill_kernel(const int* __restrict__ ei) {
    int e = blockIdx.x * blockDim.x + threadIdx.x;
    if (e < EE) {
        int s = ei[e];
        int d = ei[EE + e];
        int pos = atomicAdd(&g_fill[d], 1);
        g_csr[g_rowptr[d] + pos] = s;
    }
}

// ---------------- GEMM1 via mma.sync bf16 (3-term hi/lo split) + fused attn1 ----
// Block: 256 thr = 8 warps = 4 row-tiles(32) x 2 col-tiles(64). Tile 128x128.
// K chunked x64 through smem. A smem [row][kpair] word-stride 36 (conflict-free
// frag reads: banks 4*(l/4)+(l%4)). B smem transposed [kpair][j] word-stride 136
// (frag reads: banks 8*(l%4)+(l/4)).

#define A_STRIDE 36    // words per A row (32 kpairs + pad)
#define B_STRIDE 136   // words per B kpair-row (128 j + pad)
#define SM_AHI 0
#define SM_ALO (128 * A_STRIDE)            // 4608 words
#define SM_BHI (2 * 128 * A_STRIDE)        // 9216
#define SM_BLO (2 * 128 * A_STRIDE + 32 * B_STRIDE)   // 13568
#define SM_WORDS (2 * 128 * A_STRIDE + 2 * 32 * B_STRIDE)  // 17920 words = 71680 B

__device__ __forceinline__ void mma_bf16(float* c, const uint32_t* a, uint32_t b0, uint32_t b1) {
    asm volatile(
        "mma.sync.aligned.m16n8k16.row.col.f32.bf16.bf16.f32 "
        "{%0,%1,%2,%3}, {%4,%5,%6,%7}, {%8,%9}, {%0,%1,%2,%3};"
        : "+f"(c[0]), "+f"(c[1]), "+f"(c[2]), "+f"(c[3])
        : "r"(a[0]), "r"(a[1]), "r"(a[2]), "r"(a[3]), "r"(b0), "r"(b1));
}

__device__ __forceinline__ uint32_t pack_bf2(float a, float b) {
    __nv_bfloat162 h = __floats2bfloat162_rn(a, b);
    return *(uint32_t*)&h;
}

__global__ void __launch_bounds__(256, 1)
gemm1_mma_kernel(const float* __restrict__ x, const float* __restrict__ W1,
                 const float* __restrict__ as, const float* __restrict__ ad) {
    extern __shared__ uint32_t sm[];
    uint32_t* Ahi = sm + SM_AHI;
    uint32_t* Alo = sm + SM_ALO;
    uint32_t* Bhi = sm + SM_BHI;
    uint32_t* Blo = sm + SM_BLO;

    int t = threadIdx.x, wid = t >> 5, lane = t & 31;
    int wr = wid & 3, wc = wid >> 2;           // row-tile, col-tile
    int nbase = blockIdx.x * 128;

    float c[2][8][4];
#pragma unroll
    for (int rs = 0; rs < 2; rs++)
#pragma unroll
        for (int nf = 0; nf < 8; nf++)
#pragma unroll
            for (int q = 0; q < 4; q++) c[rs][nf][q] = 0.f;

    for (int kc = 0; kc < 2; kc++) {
        if (kc) __syncthreads();   // protect previous chunk's reads
        // --- A chunk: x[nbase..+127][kc*64..+63] -> hi/lo bf16, [row][kpair] ---
#pragma unroll
        for (int i = 0; i < 8; i++) {
            int idx = t + 256 * i;          // 2048 float4
            int r = idx >> 4, c4 = idx & 15;
            int node = nbase + r;
            float4 v = make_float4(0.f, 0.f, 0.f, 0.f);
            if (node < NN) v = ((const float4*)x)[node * 32 + kc * 16 + c4];
            uint32_t h0 = pack_bf2(v.x, v.y), h1 = pack_bf2(v.z, v.w);
            __nv_bfloat162 hh0 = *(__nv_bfloat162*)&h0;
            __nv_bfloat162 hh1 = *(__nv_bfloat162*)&h1;
            uint32_t l0 = pack_bf2(v.x - __bfloat162float(hh0.x), v.y - __bfloat162float(hh0.y));
            uint32_t l1 = pack_bf2(v.z - __bfloat162float(hh1.x), v.w - __bfloat162float(hh1.y));
            int w = r * A_STRIDE + c4 * 2;
            Ahi[w] = h0; Ahi[w + 1] = h1;
            Alo[w] = l0; Alo[w + 1] = l1;
        }
        // --- B chunk: W1[kc*64+k][j] -> transposed [kpair][j], hi/lo ---
#pragma unroll
        for (int i = 0; i < 32; i++) {
            int idx = t + 256 * i;          // 8192 elems
            int k = idx >> 7, j = idx & 127;
            float w = W1[(kc * 64 + k) * 128 + j];
            __nv_bfloat16 hi = __float2bfloat16(w);
            __nv_bfloat16 lo = __float2bfloat16(w - __bfloat162float(hi));
            int word = (k >> 1) * B_STRIDE + j;
            ((__nv_bfloat16*)(Bhi + word))[k & 1] = hi;
            ((__nv_bfloat16*)(Blo + word))[k & 1] = lo;
        }
        __syncthreads();

        // --- 4 ksteps of m16n8k16 ---
#pragma unroll
        for (int kk = 0; kk < 4; kk++) {
            uint32_t ah[2][4], al[2][4];
#pragma unroll
            for (int rs = 0; rs < 2; rs++) {
                int row = wr * 32 + rs * 16 + (lane >> 2);
                int base = row * A_STRIDE + kk * 8 + (lane & 3);
                ah[rs][0] = Ahi[base];
                ah[rs][1] = Ahi[base + 8 * A_STRIDE];
                ah[rs][2] = Ahi[base + 4];
                ah[rs][3] = Ahi[base + 8 * A_STRIDE + 4];
                al[rs][0] = Alo[base];
                al[rs][1] = Alo[base + 8 * A_STRIDE];
                al[rs][2] = Alo[base + 4];
                al[rs][3] = Alo[base + 8 * A_STRIDE + 4];
            }
#pragma unroll
            for (int nf = 0; nf < 8; nf++) {
                int j = wc * 64 + nf * 8 + (lane >> 2);
                int bw = (kk * 8 + (lane & 3)) * B_STRIDE + j;
                uint32_t bh0 = Bhi[bw], bh1 = Bhi[bw + 4 * B_STRIDE];
                uint32_t bl0 = Blo[bw], bl1 = Blo[bw + 4 * B_STRIDE];
#pragma unroll
                for (int rs = 0; rs < 2; rs++) {
                    mma_bf16(c[rs][nf], ah[rs], bh0, bh1);   // hi*hi
                    mma_bf16(c[rs][nf], ah[rs], bl0, bl1);   // hi*lo
                    mma_bf16(c[rs][nf], al[rs], bh0, bh1);   // lo*hi
                }
            }
        }
    }

    // --- epilogue: store H1 + fused attn1 (heads wc*4..wc*4+3) ---
#pragma unroll
    for (int rs = 0; rs < 2; rs++) {
#pragma unroll
        for (int hh = 0; hh < 2; hh++) {
            int row = wr * 32 + rs * 16 + (lane >> 2) + hh * 8;
            int node = nbase + row;
            float ss[4] = {0.f, 0.f, 0.f, 0.f};
            float dd[4] = {0.f, 0.f, 0.f, 0.f};
#pragma unroll
            for (int nf = 0; nf < 8; nf++) {
                float v0 = c[rs][nf][hh * 2];
                float v1 = c[rs][nf][hh * 2 + 1];
                int col = wc * 64 + nf * 8 + (lane & 3) * 2;
                if (node < NN)
                    *(float2*)&g_H1[node * 128 + col] = make_float2(v0, v1);
                int hp = nf >> 1;                              // local head 0..3
                int wcol = (nf & 1) * 8 + (lane & 3) * 2;       // col within head
                int hb = (wc * 4 + hp) * 16 + wcol;
                ss[hp] += v0 * __ldg(&as[hb]) + v1 * __ldg(&as[hb + 1]);
                dd[hp] += v0 * __ldg(&ad[hb]) + v1 * __ldg(&ad[hb + 1]);
            }
#pragma unroll
            for (int hp = 0; hp < 4; hp++) {
                ss[hp] += __shfl_xor_sync(0xffffffffu, ss[hp], 1);
                ss[hp] += __shfl_xor_sync(0xffffffffu, ss[hp], 2);
                dd[hp] += __shfl_xor_sync(0xffffffffu, dd[hp], 1);
                dd[hp] += __shfl_xor_sync(0xffffffffu, dd[hp], 2);
            }
            if ((lane & 3) == 0 && node < NN) {
#pragma unroll
                for (int hp = 0; hp < 4; hp++) {
                    g_asrc1[node * 8 + wc * 4 + hp] = ss[hp];
                    g_adst1[node * 8 + wc * 4 + hp] = dd[hp];
                }
            }
        }
    }
}

// ---------------- layer-1 aggregation: warp per dst, single pass, unroll 4 ----
__global__ void agg1_kernel(const float* __restrict__ b1) {
    int w = (blockIdx.x * blockDim.x + threadIdx.x) >> 5;
    int l = threadIdx.x & 31;
    if (w >= NN) return;
    int d = w;
    int start = g_rowptr[d], end = g_rowptr[d + 1];
    int hl = l >> 2;

    float adh = __ldg(&g_adst1[d * 8 + hl]);
    float wself = __expf(lrelu(__ldg(&g_asrc1[d * 8 + hl]) + adh));

    float den0 = wself, den1 = 0.f, den2 = 0.f, den3 = 0.f;
    float4 acc0, acc1, acc2, acc3;
    {
        float4 v = __ldg(((const float4*)g_H1) + d * 32 + l);
        acc0.x = wself * v.x; acc0.y = wself * v.y;
        acc0.z = wself * v.z; acc0.w = wself * v.w;
        acc1 = make_float4(0.f, 0.f, 0.f, 0.f);
        acc2 = make_float4(0.f, 0.f, 0.f, 0.f);
        acc3 = make_float4(0.f, 0.f, 0.f, 0.f);
    }

    int e = start;
    for (; e + 3 < end; e += 4) {
        int s0 = g_csr[e];
        int s1 = g_csr[e + 1];
        int s2 = g_csr[e + 2];
        int s3 = g_csr[e + 3];
        float w0 = __expf(lrelu(__ldg(&g_asrc1[s0 * 8 + hl]) + adh));
        float w1 = __expf(lrelu(__ldg(&g_asrc1[s1 * 8 + hl]) + adh));
        float w2 = __expf(lrelu(__ldg(&g_asrc1[s2 * 8 + hl]) + adh));
        float w3 = __expf(lrelu(__ldg(&g_asrc1[s3 * 8 + hl]) + adh));
        float4 v0 = __ldg(((const float4*)g_H1) + s0 * 32 + l);
        float4 v1 = __ldg(((const float4*)g_H1) + s1 * 32 + l);
        float4 v2 = __ldg(((const float4*)g_H1) + s2 * 32 + l);
        float4 v3 = __ldg(((const float4*)g_H1) + s3 * 32 + l);
        den0 += w0; den1 += w1; den2 += w2; den3 += w3;
        acc0.x += w0 * v0.x; acc0.y += w0 * v0.y; acc0.z += w0 * v0.z; acc0.w += w0 * v0.w;
        acc1.x += w1 * v1.x; acc1.y += w1 * v1.y; acc1.z += w1 * v1.z; acc1.w += w1 * v1.w;
        acc2.x += w2 * v2.x; acc2.y += w2 * v2.y; acc2.z += w2 * v2.z; acc2.w += w2 * v2.w;
        acc3.x += w3 * v3.x; acc3.y += w3 * v3.y; acc3.z += w3 * v3.z; acc3.w += w3 * v3.w;
    }
    for (; e < end; e++) {
        int s0 = g_csr[e];
        float w0 = __expf(lrelu(__ldg(&g_asrc1[s0 * 8 + hl]) + adh));
        float4 v0 = __ldg(((const float4*)g_H1) + s0 * 32 + l);
        den0 += w0;
        acc0.x += w0 * v0.x; acc0.y += w0 * v0.y;
        acc0.z += w0 * v0.z; acc0.w += w0 * v0.w;
    }

    float inv = 1.f / ((den0 + den1) + (den2 + den3));
    float4 bb = ((const float4*)b1)[l];
    float4 r;
    r.x = ((acc0.x + acc1.x) + (acc2.x + acc3.x)) * inv + bb.x;
    r.y = ((acc0.y + acc1.y) + (acc2.y + acc3.y)) * inv + bb.y;
    r.z = ((acc0.z + acc1.z) + (acc2.z + acc3.z)) * inv + bb.z;
    r.w = ((acc0.w + acc1.w) + (acc2.w + acc3.w)) * inv + bb.w;
    r.x = r.x > 0.f ? r.x : __expf(r.x) - 1.f;
    r.y = r.y > 0.f ? r.y : __expf(r.y) - 1.f;
    r.z = r.z > 0.f ? r.z : __expf(r.z) - 1.f;
    r.w = r.w > 0.f ? r.w : __expf(r.w) - 1.f;
    ((float4*)g_out1)[d * 32 + l] = r;
}

// ---------------- GEMM2 + fused attn2 ----------------
__global__ void gemm2_kernel(const float* __restrict__ W2,
                             const float* __restrict__ as2, const float* __restrict__ ad2) {
    __shared__ float sx[32 * 132];
    __shared__ float sW[128 * NCLS];
    int t = threadIdx.x;
    int nl = t >> 3, cg = t & 7;
    int nbase = blockIdx.x * 32;

#pragma unroll
    for (int i = 0; i < 4; i++) {
        int idx = t + 256 * i;
        int r = idx >> 5, c4 = idx & 31;
        int gn = nbase + r;
        float4 v = make_float4(0.f, 0.f, 0.f, 0.f);
        if (gn < NN) v = ((const float4*)g_out1)[gn * 32 + c4];
        float* dst = &sx[r * 132 + c4 * 4];
        dst[0] = v.x; dst[1] = v.y; dst[2] = v.z; dst[3] = v.w;
    }
    for (int i = t; i < 128 * NCLS; i += 256) sW[i] = W2[i];
    __syncthreads();

    float acc[5] = {0.f, 0.f, 0.f, 0.f, 0.f};
    const float* wp = &sW[cg * 5];
    const float* xp = &sx[nl * 132];
#pragma unroll 4
    for (int k = 0; k < 128; k++) {
        float xv = xp[k];
#pragma unroll
        for (int j = 0; j < 5; j++)
            acc[j] += xv * wp[k * NCLS + j];
    }
    int node = nbase + nl;
    // fused attn2: per-node dot with att vectors, reduce over the 8 cg lanes
    float ps = 0.f, pd = 0.f;
#pragma unroll
    for (int j = 0; j < 5; j++) {
        ps += acc[j] * __ldg(&as2[cg * 5 + j]);
        pd += acc[j] * __ldg(&ad2[cg * 5 + j]);
    }
#pragma unroll
    for (int off = 1; off < 8; off <<= 1) {
        ps += __shfl_xor_sync(0xffffffffu, ps, off);
        pd += __shfl_xor_sync(0xffffffffu, pd, off);
    }
    if (node < NN) {
#pragma unroll
        for (int j = 0; j < 5; j++)
            g_H2[node * NCLS + cg * 5 + j] = acc[j];
        if (cg == 0) {
            g_asrc2[node] = ps;
            g_adst2[node] = pd;
        }
    }
}

// ---------------- layer-2 aggregation: warp per dst, single pass ----------------
__global__ void agg2_kernel(const float* __restrict__ b2, float* __restrict__ out) {
    int w = (blockIdx.x * blockDim.x + threadIdx.x) >> 5;
    int l = threadIdx.x & 31;
    if (w >= NN) return;
    int d = w;
    int start = g_rowptr[d], end = g_rowptr[d + 1];

    float adst = __ldg(&g_adst2[d]);
    float wself = __expf(lrelu(__ldg(&g_asrc2[d]) + adst));

    float den0 = wself, den1 = 0.f;
    float accA0 = wself * __ldg(&g_H2[d * NCLS + l]);
    float accA1 = 0.f;
    float accB0 = (l < 8) ? wself * __ldg(&g_H2[d * NCLS + 32 + l]) : 0.f;
    float accB1 = 0.f;

    int e = start;
    for (; e + 1 < end; e += 2) {
        int s0 = g_csr[e];
        int s1 = g_csr[e + 1];
        float w0 = __expf(lrelu(__ldg(&g_asrc2[s0]) + adst));
        float w1 = __expf(lrelu(__ldg(&g_asrc2[s1]) + adst));
        den0 += w0; den1 += w1;
        accA0 += w0 * __ldg(&g_H2[s0 * NCLS + l]);
        accA1 += w1 * __ldg(&g_H2[s1 * NCLS + l]);
        if (l < 8) {
            accB0 += w0 * __ldg(&g_H2[s0 * NCLS + 32 + l]);
            accB1 += w1 * __ldg(&g_H2[s1 * NCLS + 32 + l]);
        }
    }
    if (e < end) {
        int s0 = g_csr[e];
        float w0 = __expf(lrelu(__ldg(&g_asrc2[s0]) + adst));
        den0 += w0;
        accA0 += w0 * __ldg(&g_H2[s0 * NCLS + l]);
        if (l < 8) accB0 += w0 * __ldg(&g_H2[s0 * NCLS + 32 + l]);
    }

    float inv = 1.f / (den0 + den1);
    out[d * NCLS + l] = (accA0 + accA1) * inv + b2[l];
    if (l < 8) out[d * NCLS + 32 + l] = (accB0 + accB1) * inv + b2[32 + l];
}

// ---------------- launch ----------------
static cudaStream_t g_s2 = nullptr;
static cudaEvent_t g_evFork = nullptr, g_evJoin = nullptr;

extern "C" void kernel_launch(void* const* d_in, const int* in_sizes, int n_in,
                              void* d_out, int out_size) {
    const float* x   = (const float*)d_in[0];
    const int*   ei  = (const int*)d_in[1];     // int32 (JAX x64 disabled)
    const float* W1  = (const float*)d_in[2];
    const float* as1 = (const float*)d_in[3];
    const float* ad1 = (const float*)d_in[4];
    const float* b1  = (const float*)d_in[5];
    const float* W2  = (const float*)d_in[6];
    const float* as2 = (const float*)d_in[7];
    const float* ad2 = (const float*)d_in[8];
    const float* b2  = (const float*)d_in[9];
    float* out = (float*)d_out;

    if (g_s2 == nullptr) {
        cudaStreamCreateWithFlags(&g_s2, cudaStreamNonBlocking);
        cudaEventCreateWithFlags(&g_evFork, cudaEventDisableTiming);
        cudaEventCreateWithFlags(&g_evJoin, cudaEventDisableTiming);
        cudaFuncSetAttribute(gemm1_mma_kernel,
                             cudaFuncAttributeMaxDynamicSharedMemorySize,
                             SM_WORDS * 4);
    }

    // fork: CSR build on side stream
    cudaEventRecord(g_evFork, 0);
    cudaStreamWaitEvent(g_s2, g_evFork, 0);

    zero_kernel<<<(NN + 255) / 256, 256, 0, g_s2>>>();
    count_kernel<<<(EE + 255) / 256, 256, 0, g_s2>>>(ei);
    blockscan_kernel<<<NBLK, 1024, 0, g_s2>>>();
    scanbsum_kernel<<<1, 64, 0, g_s2>>>();
    addoff_kernel<<<(NN + 255) / 256, 256, 0, g_s2>>>();
    fill_kernel<<<(EE + 255) / 256, 256, 0, g_s2>>>(ei);
    cudaEventRecord(g_evJoin, g_s2);

    // main stream: tensor-core GEMM1 with fused attn1
    gemm1_mma_kernel<<<(NN + 127) / 128, 256, SM_WORDS * 4>>>(x, W1, as1, ad1);

    // join: aggregation needs both
    cudaStreamWaitEvent(0, g_evJoin, 0);
    agg1_kernel<<<(NN * 32 + 255) / 256, 256>>>(b1);

    gemm2_kernel<<<(NN + 31) / 32, 256>>>(W2, as2, ad2);
    agg2_kernel<<<(NN * 32 + 255) / 256, 256>>>(b2, out);
}

// round 10
// speedup vs baseline: 2.3813x; 1.0800x over previous
#include <cuda_runtime.h>
#include <cuda_bf16.h>
#include <cstdint>

#define NN 50000
#define EE 800000
#define NCLS 40
#define NBLK 49   // ceil(NN/1024)

// ---------------- device scratch (static, allocation-free) ----------------
__device__ __align__(16) float g_H1[NN * 128];    // layer1 features h = x@W1
__device__ __align__(16) float g_out1[NN * 128];  // layer1 output after ELU
__device__ __align__(16) float g_H2[NN * NCLS];   // layer2 features
__device__ __align__(16) float g_asrc1[NN * 8];
__device__ __align__(16) float g_adst1[NN * 8];
__device__ float g_asrc2[NN];
__device__ float g_adst2[NN];
__device__ int g_deg[NN];        // self-restoring: count adds, fill subtracts
__device__ int g_rowptr[NN + 1];
__device__ int g_csr[EE];
__device__ int g_bsum[64];

__device__ __forceinline__ float lrelu(float x) { return x > 0.f ? x : 0.2f * x; }

// ---------------- CSR build ----------------
__global__ void count_kernel(const int* __restrict__ ei) {
    int q = blockIdx.x * blockDim.x + threadIdx.x;
    if (q < EE / 4) {
        int4 d4 = __ldg((const int4*)(ei + EE) + q);
        atomicAdd(&g_deg[d4.x], 1);
        atomicAdd(&g_deg[d4.y], 1);
        atomicAdd(&g_deg[d4.z], 1);
        atomicAdd(&g_deg[d4.w], 1);
    }
}

__global__ void blockscan_kernel() {
    __shared__ int wsum[32];
    int b = blockIdx.x, t = threadIdx.x;
    int i = b * 1024 + t;
    int lane = t & 31, wid = t >> 5;
    int x = (i < NN) ? g_deg[i] : 0;
#pragma unroll
    for (int off = 1; off < 32; off <<= 1) {
        int y = __shfl_up_sync(0xffffffffu, x, off);
        if (lane >= off) x += y;
    }
    if (lane == 31) wsum[wid] = x;
    __syncthreads();
    if (wid == 0) {
        int s = wsum[lane];
#pragma unroll
        for (int off = 1; off < 32; off <<= 1) {
            int y = __shfl_up_sync(0xffffffffu, s, off);
            if (lane >= off) s += y;
        }
        wsum[lane] = s;
    }
    __syncthreads();
    int incl = x + (wid > 0 ? wsum[wid - 1] : 0);
    if (i < NN) g_rowptr[i + 1] = incl;
    if (t == 1023) g_bsum[b] = incl;
}

// addoff with inlined block-sum prefix (each block reduces g_bsum[0..b-1])
__global__ void addoff_kernel() {
    __shared__ int s_off;
    int b = blockIdx.x, t = threadIdx.x;
    if (t < 32) {
        int v = (t < b) ? g_bsum[t] : 0;
        if (t + 32 < b) v += g_bsum[t + 32];
#pragma unroll
        for (int off = 16; off > 0; off >>= 1)
            v += __shfl_xor_sync(0xffffffffu, v, off);
        if (t == 0) s_off = v;
    }
    __syncthreads();
    int i = b * 1024 + t;
    if (i < NN) g_rowptr[i + 1] += s_off;
    if (i == 0) g_rowptr[0] = 0;
}

__global__ void fill_kernel(const int* __restrict__ ei) {
    int q = blockIdx.x * blockDim.x + threadIdx.x;
    if (q < EE / 4) {
        int4 s4 = __ldg((const int4*)ei + q);
        int4 d4 = __ldg((const int4*)(ei + EE) + q);
        int p;
        p = atomicSub(&g_deg[d4.x], 1); g_csr[g_rowptr[d4.x] + p - 1] = s4.x;
        p = atomicSub(&g_deg[d4.y], 1); g_csr[g_rowptr[d4.y] + p - 1] = s4.y;
        p = atomicSub(&g_deg[d4.z], 1); g_csr[g_rowptr[d4.z] + p - 1] = s4.z;
        p = atomicSub(&g_deg[d4.w], 1); g_csr[g_rowptr[d4.w] + p - 1] = s4.w;
    }
}

// ---------------- shared MMA helpers ----------------
__device__ __forceinline__ void mma_bf16(float* c, const uint32_t* a, uint32_t b0, uint32_t b1) {
    asm volatile(
        "mma.sync.aligned.m16n8k16.row.col.f32.bf16.bf16.f32 "
        "{%0,%1,%2,%3}, {%4,%5,%6,%7}, {%8,%9}, {%0,%1,%2,%3};"
        : "+f"(c[0]), "+f"(c[1]), "+f"(c[2]), "+f"(c[3])
        : "r"(a[0]), "r"(a[1]), "r"(a[2]), "r"(a[3]), "r"(b0), "r"(b1));
}

__device__ __forceinline__ uint32_t pack_bf2(float a, float b) {
    __nv_bfloat162 h = __floats2bfloat162_rn(a, b);
    return *(uint32_t*)&h;
}

// ---------------- GEMM1 via mma.sync bf16 (3-term hi/lo split) + fused attn1 ----
#define A_STRIDE 36
#define B_STRIDE 136
#define SM_AHI 0
#define SM_ALO (128 * A_STRIDE)
#define SM_BHI (2 * 128 * A_STRIDE)
#define SM_BLO (2 * 128 * A_STRIDE + 32 * B_STRIDE)
#define SM_WORDS (2 * 128 * A_STRIDE + 2 * 32 * B_STRIDE)

__global__ void __launch_bounds__(256, 1)
gemm1_mma_kernel(const float* __restrict__ x, const float* __restrict__ W1,
                 const float* __restrict__ as, const float* __restrict__ ad) {
    extern __shared__ uint32_t sm[];
    uint32_t* Ahi = sm + SM_AHI;
    uint32_t* Alo = sm + SM_ALO;
    uint32_t* Bhi = sm + SM_BHI;
    uint32_t* Blo = sm + SM_BLO;

    int t = threadIdx.x, wid = t >> 5, lane = t & 31;
    int wr = wid & 3, wc = wid >> 2;
    int nbase = blockIdx.x * 128;

    float c[2][8][4];
#pragma unroll
    for (int rs = 0; rs < 2; rs++)
#pragma unroll
        for (int nf = 0; nf < 8; nf++)
#pragma unroll
            for (int q = 0; q < 4; q++) c[rs][nf][q] = 0.f;

    for (int kc = 0; kc < 2; kc++) {
        if (kc) __syncthreads();
#pragma unroll
        for (int i = 0; i < 8; i++) {
            int idx = t + 256 * i;
            int r = idx >> 4, c4 = idx & 15;
            int node = nbase + r;
            float4 v = make_float4(0.f, 0.f, 0.f, 0.f);
            if (node < NN) v = ((const float4*)x)[node * 32 + kc * 16 + c4];
            uint32_t h0 = pack_bf2(v.x, v.y), h1 = pack_bf2(v.z, v.w);
            __nv_bfloat162 hh0 = *(__nv_bfloat162*)&h0;
            __nv_bfloat162 hh1 = *(__nv_bfloat162*)&h1;
            uint32_t l0 = pack_bf2(v.x - __bfloat162float(hh0.x), v.y - __bfloat162float(hh0.y));
            uint32_t l1 = pack_bf2(v.z - __bfloat162float(hh1.x), v.w - __bfloat162float(hh1.y));
            int w = r * A_STRIDE + c4 * 2;
            Ahi[w] = h0; Ahi[w + 1] = h1;
            Alo[w] = l0; Alo[w + 1] = l1;
        }
#pragma unroll
        for (int i = 0; i < 32; i++) {
            int idx = t + 256 * i;
            int k = idx >> 7, j = idx & 127;
            float w = W1[(kc * 64 + k) * 128 + j];
            __nv_bfloat16 hi = __float2bfloat16(w);
            __nv_bfloat16 lo = __float2bfloat16(w - __bfloat162float(hi));
            int word = (k >> 1) * B_STRIDE + j;
            ((__nv_bfloat16*)(Bhi + word))[k & 1] = hi;
            ((__nv_bfloat16*)(Blo + word))[k & 1] = lo;
        }
        __syncthreads();

#pragma unroll
        for (int kk = 0; kk < 4; kk++) {
            uint32_t ah[2][4], al[2][4];
#pragma unroll
            for (int rs = 0; rs < 2; rs++) {
                int row = wr * 32 + rs * 16 + (lane >> 2);
                int base = row * A_STRIDE + kk * 8 + (lane & 3);
                ah[rs][0] = Ahi[base];
                ah[rs][1] = Ahi[base + 8 * A_STRIDE];
                ah[rs][2] = Ahi[base + 4];
                ah[rs][3] = Ahi[base + 8 * A_STRIDE + 4];
                al[rs][0] = Alo[base];
                al[rs][1] = Alo[base + 8 * A_STRIDE];
                al[rs][2] = Alo[base + 4];
                al[rs][3] = Alo[base + 8 * A_STRIDE + 4];
            }
#pragma unroll
            for (int nf = 0; nf < 8; nf++) {
                int j = wc * 64 + nf * 8 + (lane >> 2);
                int bw = (kk * 8 + (lane & 3)) * B_STRIDE + j;
                uint32_t bh0 = Bhi[bw], bh1 = Bhi[bw + 4 * B_STRIDE];
                uint32_t bl0 = Blo[bw], bl1 = Blo[bw + 4 * B_STRIDE];
#pragma unroll
                for (int rs = 0; rs < 2; rs++) {
                    mma_bf16(c[rs][nf], ah[rs], bh0, bh1);
                    mma_bf16(c[rs][nf], ah[rs], bl0, bl1);
                    mma_bf16(c[rs][nf], al[rs], bh0, bh1);
                }
            }
        }
    }

#pragma unroll
    for (int rs = 0; rs < 2; rs++) {
#pragma unroll
        for (int hh = 0; hh < 2; hh++) {
            int row = wr * 32 + rs * 16 + (lane >> 2) + hh * 8;
            int node = nbase + row;
            float ss[4] = {0.f, 0.f, 0.f, 0.f};
            float dd[4] = {0.f, 0.f, 0.f, 0.f};
#pragma unroll
            for (int nf = 0; nf < 8; nf++) {
                float v0 = c[rs][nf][hh * 2];
                float v1 = c[rs][nf][hh * 2 + 1];
                int col = wc * 64 + nf * 8 + (lane & 3) * 2;
                if (node < NN)
                    *(float2*)&g_H1[node * 128 + col] = make_float2(v0, v1);
                int hp = nf >> 1;
                int wcol = (nf & 1) * 8 + (lane & 3) * 2;
                int hb = (wc * 4 + hp) * 16 + wcol;
                ss[hp] += v0 * __ldg(&as[hb]) + v1 * __ldg(&as[hb + 1]);
                dd[hp] += v0 * __ldg(&ad[hb]) + v1 * __ldg(&ad[hb + 1]);
            }
#pragma unroll
            for (int hp = 0; hp < 4; hp++) {
                ss[hp] += __shfl_xor_sync(0xffffffffu, ss[hp], 1);
                ss[hp] += __shfl_xor_sync(0xffffffffu, ss[hp], 2);
                dd[hp] += __shfl_xor_sync(0xffffffffu, dd[hp], 1);
                dd[hp] += __shfl_xor_sync(0xffffffffu, dd[hp], 2);
            }
            if ((lane & 3) == 0 && node < NN) {
#pragma unroll
                for (int hp = 0; hp < 4; hp++) {
                    g_asrc1[node * 8 + wc * 4 + hp] = ss[hp];
                    g_adst1[node * 8 + wc * 4 + hp] = dd[hp];
                }
            }
        }
    }
}

// ---------------- layer-1 aggregation: warp per dst, single pass, unroll 4 ----
__global__ void agg1_kernel(const float* __restrict__ b1) {
    int w = (blockIdx.x * blockDim.x + threadIdx.x) >> 5;
    int l = threadIdx.x & 31;
    if (w >= NN) return;
    int d = w;
    int start = g_rowptr[d], end = g_rowptr[d + 1];
    int hl = l >> 2;

    float adh = __ldg(&g_adst1[d * 8 + hl]);
    float wself = __expf(lrelu(__ldg(&g_asrc1[d * 8 + hl]) + adh));

    float den0 = wself, den1 = 0.f, den2 = 0.f, den3 = 0.f;
    float4 acc0, acc1, acc2, acc3;
    {
        float4 v = __ldg(((const float4*)g_H1) + d * 32 + l);
        acc0.x = wself * v.x; acc0.y = wself * v.y;
        acc0.z = wself * v.z; acc0.w = wself * v.w;
        acc1 = make_float4(0.f, 0.f, 0.f, 0.f);
        acc2 = make_float4(0.f, 0.f, 0.f, 0.f);
        acc3 = make_float4(0.f, 0.f, 0.f, 0.f);
    }

    int e = start;
    for (; e + 3 < end; e += 4) {
        int s0 = __ldg(&g_csr[e]);
        int s1 = __ldg(&g_csr[e + 1]);
        int s2 = __ldg(&g_csr[e + 2]);
        int s3 = __ldg(&g_csr[e + 3]);
        float w0 = __expf(lrelu(__ldg(&g_asrc1[s0 * 8 + hl]) + adh));
        float w1 = __expf(lrelu(__ldg(&g_asrc1[s1 * 8 + hl]) + adh));
        float w2 = __expf(lrelu(__ldg(&g_asrc1[s2 * 8 + hl]) + adh));
        float w3 = __expf(lrelu(__ldg(&g_asrc1[s3 * 8 + hl]) + adh));
        float4 v0 = __ldg(((const float4*)g_H1) + s0 * 32 + l);
        float4 v1 = __ldg(((const float4*)g_H1) + s1 * 32 + l);
        float4 v2 = __ldg(((const float4*)g_H1) + s2 * 32 + l);
        float4 v3 = __ldg(((const float4*)g_H1) + s3 * 32 + l);
        den0 += w0; den1 += w1; den2 += w2; den3 += w3;
        acc0.x += w0 * v0.x; acc0.y += w0 * v0.y; acc0.z += w0 * v0.z; acc0.w += w0 * v0.w;
        acc1.x += w1 * v1.x; acc1.y += w1 * v1.y; acc1.z += w1 * v1.z; acc1.w += w1 * v1.w;
        acc2.x += w2 * v2.x; acc2.y += w2 * v2.y; acc2.z += w2 * v2.z; acc2.w += w2 * v2.w;
        acc3.x += w3 * v3.x; acc3.y += w3 * v3.y; acc3.z += w3 * v3.z; acc3.w += w3 * v3.w;
    }
    for (; e < end; e++) {
        int s0 = __ldg(&g_csr[e]);
        float w0 = __expf(lrelu(__ldg(&g_asrc1[s0 * 8 + hl]) + adh));
        float4 v0 = __ldg(((const float4*)g_H1) + s0 * 32 + l);
        den0 += w0;
        acc0.x += w0 * v0.x; acc0.y += w0 * v0.y;
        acc0.z += w0 * v0.z; acc0.w += w0 * v0.w;
    }

    float inv = 1.f / ((den0 + den1) + (den2 + den3));
    float4 bb = ((const float4*)b1)[l];
    float4 r;
    r.x = ((acc0.x + acc1.x) + (acc2.x + acc3.x)) * inv + bb.x;
    r.y = ((acc0.y + acc1.y) + (acc2.y + acc3.y)) * inv + bb.y;
    r.z = ((acc0.z + acc1.z) + (acc2.z + acc3.z)) * inv + bb.z;
    r.w = ((acc0.w + acc1.w) + (acc2.w + acc3.w)) * inv + bb.w;
    r.x = r.x > 0.f ? r.x : __expf(r.x) - 1.f;
    r.y = r.y > 0.f ? r.y : __expf(r.y) - 1.f;
    r.z = r.z > 0.f ? r.z : __expf(r.z) - 1.f;
    r.w = r.w > 0.f ? r.w : __expf(r.w) - 1.f;
    ((float4*)g_out1)[d * 32 + l] = r;
}

// ---------------- GEMM2 via mma.sync bf16 split + fused attn2 ----------------
// 128 nodes/block, 8 warps x 16 rows, 40 cols (5 n-frags), K=128.
#define A2_STRIDE 68
#define B2_STRIDE 44
#define SM2_ALO (128 * A2_STRIDE)
#define SM2_BHI (2 * 128 * A2_STRIDE)
#define SM2_BLO (2 * 128 * A2_STRIDE + 64 * B2_STRIDE)
#define SM2_WORDS (2 * 128 * A2_STRIDE + 2 * 64 * B2_STRIDE)

__global__ void __launch_bounds__(256, 1)
gemm2_mma_kernel(const float* __restrict__ W2,
                 const float* __restrict__ as2, const float* __restrict__ ad2) {
    extern __shared__ uint32_t sm[];
    uint32_t* Ahi = sm;
    uint32_t* Alo = sm + SM2_ALO;
    uint32_t* Bhi = sm + SM2_BHI;
    uint32_t* Blo = sm + SM2_BLO;

    int t = threadIdx.x, wid = t >> 5, lane = t & 31;
    int nbase = blockIdx.x * 128;

    // A: g_out1 tile [128][128] -> hi/lo, [row][kpair] stride 68
#pragma unroll
    for (int i = 0; i < 16; i++) {
        int idx = t + 256 * i;
        int r = idx >> 5, c4 = idx & 31;
        int node = nbase + r;
        float4 v = make_float4(0.f, 0.f, 0.f, 0.f);
        if (node < NN) v = ((const float4*)g_out1)[node * 32 + c4];
        uint32_t h0 = pack_bf2(v.x, v.y), h1 = pack_bf2(v.z, v.w);
        __nv_bfloat162 hh0 = *(__nv_bfloat162*)&h0;
        __nv_bfloat162 hh1 = *(__nv_bfloat162*)&h1;
        uint32_t l0 = pack_bf2(v.x - __bfloat162float(hh0.x), v.y - __bfloat162float(hh0.y));
        uint32_t l1 = pack_bf2(v.z - __bfloat162float(hh1.x), v.w - __bfloat162float(hh1.y));
        int w = r * A2_STRIDE + c4 * 2;
        Ahi[w] = h0; Ahi[w + 1] = h1;
        Alo[w] = l0; Alo[w + 1] = l1;
    }
    // B: W2[k][j] k=128, j=40 -> [kpair][j] stride 44
    for (int idx = t; idx < 128 * NCLS; idx += 256) {
        int k = idx / NCLS, j = idx % NCLS;
        float w = W2[idx];
        __nv_bfloat16 hi = __float2bfloat16(w);
        __nv_bfloat16 lo = __float2bfloat16(w - __bfloat162float(hi));
        int word = (k >> 1) * B2_STRIDE + j;
        ((__nv_bfloat16*)(Bhi + word))[k & 1] = hi;
        ((__nv_bfloat16*)(Blo + word))[k & 1] = lo;
    }
    __syncthreads();

    float c[5][4];
#pragma unroll
    for (int nf = 0; nf < 5; nf++)
#pragma unroll
        for (int q = 0; q < 4; q++) c[nf][q] = 0.f;

#pragma unroll
    for (int kk = 0; kk < 8; kk++) {
        int base = (wid * 16 + (lane >> 2)) * A2_STRIDE + kk * 8 + (lane & 3);
        uint32_t ah[4], al[4];
        ah[0] = Ahi[base];
        ah[1] = Ahi[base + 8 * A2_STRIDE];
        ah[2] = Ahi[base + 4];
        ah[3] = Ahi[base + 8 * A2_STRIDE + 4];
        al[0] = Alo[base];
        al[1] = Alo[base + 8 * A2_STRIDE];
        al[2] = Alo[base + 4];
        al[3] = Alo[base + 8 * A2_STRIDE + 4];
#pragma unroll
        for (int nf = 0; nf < 5; nf++) {
            int j = nf * 8 + (lane >> 2);
            int bw = (kk * 8 + (lane & 3)) * B2_STRIDE + j;
            uint32_t bh0 = Bhi[bw], bh1 = Bhi[bw + 4 * B2_STRIDE];
            uint32_t bl0 = Blo[bw], bl1 = Blo[bw + 4 * B2_STRIDE];
            mma_bf16(c[nf], ah, bh0, bh1);
            mma_bf16(c[nf], ah, bl0, bl1);
            mma_bf16(c[nf], al, bh0, bh1);
        }
    }

    // epilogue: store H2 + fused attn2
#pragma unroll
    for (int hh = 0; hh < 2; hh++) {
        int row = wid * 16 + (lane >> 2) + hh * 8;
        int node = nbase + row;
        float ps = 0.f, pd = 0.f;
#pragma unroll
        for (int nf = 0; nf < 5; nf++) {
            float v0 = c[nf][hh * 2];
            float v1 = c[nf][hh * 2 + 1];
            int col = nf * 8 + (lane & 3) * 2;
            if (node < NN)
                *(float2*)&g_H2[node * NCLS + col] = make_float2(v0, v1);
            ps += v0 * __ldg(&as2[col]) + v1 * __ldg(&as2[col + 1]);
            pd += v0 * __ldg(&ad2[col]) + v1 * __ldg(&ad2[col + 1]);
        }
        ps += __shfl_xor_sync(0xffffffffu, ps, 1);
        ps += __shfl_xor_sync(0xffffffffu, ps, 2);
        pd += __shfl_xor_sync(0xffffffffu, pd, 1);
        pd += __shfl_xor_sync(0xffffffffu, pd, 2);
        if ((lane & 3) == 0 && node < NN) {
            g_asrc2[node] = ps;
            g_adst2[node] = pd;
        }
    }
}

// ---------------- layer-2 aggregation: warp per dst, single pass, unroll 4 ----
__global__ void agg2_kernel(const float* __restrict__ b2, float* __restrict__ out) {
    int w = (blockIdx.x * blockDim.x + threadIdx.x) >> 5;
    int l = threadIdx.x & 31;
    if (w >= NN) return;
    int d = w;
    int start = g_rowptr[d], end = g_rowptr[d + 1];

    float adst = __ldg(&g_adst2[d]);
    float wself = __expf(lrelu(__ldg(&g_asrc2[d]) + adst));

    float den0 = wself, den1 = 0.f, den2 = 0.f, den3 = 0.f;
    float accA0 = wself * __ldg(&g_H2[d * NCLS + l]);
    float accA1 = 0.f, accA2 = 0.f, accA3 = 0.f;
    float accB0 = (l < 8) ? wself * __ldg(&g_H2[d * NCLS + 32 + l]) : 0.f;
    float accB1 = 0.f, accB2 = 0.f, accB3 = 0.f;

    int e = start;
    for (; e + 3 < end; e += 4) {
        int s0 = __ldg(&g_csr[e]);
        int s1 = __ldg(&g_csr[e + 1]);
        int s2 = __ldg(&g_csr[e + 2]);
        int s3 = __ldg(&g_csr[e + 3]);
        float w0 = __expf(lrelu(__ldg(&g_asrc2[s0]) + adst));
        float w1 = __expf(lrelu(__ldg(&g_asrc2[s1]) + adst));
        float w2 = __expf(lrelu(__ldg(&g_asrc2[s2]) + adst));
        float w3 = __expf(lrelu(__ldg(&g_asrc2[s3]) + adst));
        den0 += w0; den1 += w1; den2 += w2; den3 += w3;
        accA0 += w0 * __ldg(&g_H2[s0 * NCLS + l]);
        accA1 += w1 * __ldg(&g_H2[s1 * NCLS + l]);
        accA2 += w2 * __ldg(&g_H2[s2 * NCLS + l]);
        accA3 += w3 * __ldg(&g_H2[s3 * NCLS + l]);
        if (l < 8) {
            accB0 += w0 * __ldg(&g_H2[s0 * NCLS + 32 + l]);
            accB1 += w1 * __ldg(&g_H2[s1 * NCLS + 32 + l]);
            accB2 += w2 * __ldg(&g_H2[s2 * NCLS + 32 + l]);
            accB3 += w3 * __ldg(&g_H2[s3 * NCLS + 32 + l]);
        }
    }
    for (; e < end; e++) {
        int s0 = __ldg(&g_csr[e]);
        float w0 = __expf(lrelu(__ldg(&g_asrc2[s0]) + adst));
        den0 += w0;
        accA0 += w0 * __ldg(&g_H2[s0 * NCLS + l]);
        if (l < 8) accB0 += w0 * __ldg(&g_H2[s0 * NCLS + 32 + l]);
    }

    float inv = 1.f / ((den0 + den1) + (den2 + den3));
    out[d * NCLS + l] = ((accA0 + accA1) + (accA2 + accA3)) * inv + b2[l];
    if (l < 8) out[d * NCLS + 32 + l] = ((accB0 + accB1) + (accB2 + accB3)) * inv + b2[32 + l];
}

// ---------------- launch ----------------
static cudaStream_t g_s2 = nullptr;
static cudaEvent_t g_evFork = nullptr, g_evJoin = nullptr;

extern "C" void kernel_launch(void* const* d_in, const int* in_sizes, int n_in,
                              void* d_out, int out_size) {
    const float* x   = (const float*)d_in[0];
    const int*   ei  = (const int*)d_in[1];     // int32 (JAX x64 disabled)
    const float* W1  = (const float*)d_in[2];
    const float* as1 = (const float*)d_in[3];
    const float* ad1 = (const float*)d_in[4];
    const float* b1  = (const float*)d_in[5];
    const float* W2  = (const float*)d_in[6];
    const float* as2 = (const float*)d_in[7];
    const float* ad2 = (const float*)d_in[8];
    const float* b2  = (const float*)d_in[9];
    float* out = (float*)d_out;

    if (g_s2 == nullptr) {
        cudaStreamCreateWithFlags(&g_s2, cudaStreamNonBlocking);
        cudaEventCreateWithFlags(&g_evFork, cudaEventDisableTiming);
        cudaEventCreateWithFlags(&g_evJoin, cudaEventDisableTiming);
        cudaFuncSetAttribute(gemm1_mma_kernel,
                             cudaFuncAttributeMaxDynamicSharedMemorySize, SM_WORDS * 4);
        cudaFuncSetAttribute(gemm2_mma_kernel,
                             cudaFuncAttributeMaxDynamicSharedMemorySize, SM2_WORDS * 4);
    }

    // fork: CSR build on side stream (g_deg is self-restoring; no zero pass)
    cudaEventRecord(g_evFork, 0);
    cudaStreamWaitEvent(g_s2, g_evFork, 0);

    count_kernel<<<(EE / 4 + 255) / 256, 256, 0, g_s2>>>(ei);
    blockscan_kernel<<<NBLK, 1024, 0, g_s2>>>();
    addoff_kernel<<<NBLK, 1024, 0, g_s2>>>();
    fill_kernel<<<(EE / 4 + 255) / 256, 256, 0, g_s2>>>(ei);
    cudaEventRecord(g_evJoin, g_s2);

    // main stream: tensor-core GEMM1 with fused attn1
    gemm1_mma_kernel<<<(NN + 127) / 128, 256, SM_WORDS * 4>>>(x, W1, as1, ad1);

    // join: aggregation needs both
    cudaStreamWaitEvent(0, g_evJoin, 0);
    agg1_kernel<<<(NN * 32 + 255) / 256, 256>>>(b1);

    gemm2_mma_kernel<<<(NN + 127) / 128, 256, SM2_WORDS * 4>>>(W2, as2, ad2);
    agg2_kernel<<<(NN * 32 + 255) / 256, 256>>>(b2, out);
}